// round 2
// baseline (speedup 1.0000x reference)
#include <cuda_runtime.h>

#define NN   116
#define NE   6670
#define HID  64
#define ENCD 122
#define GRID 116

// ---- device scratch (cross-block only) ----
__device__ __align__(16) float g_z1[NN * HID];
__device__ float g_d1[NE];
__device__ float g_gE[NE * 5];
__device__ float g_dv[NN];
__device__ float g_S[NN * 5];
__device__ unsigned g_count = 0;
__device__ volatile unsigned g_sense = 0;

__device__ __forceinline__ int eix(int a, int b) {  // a < b, triu order
    return a * (231 - a) / 2 + (b - a - 1);
}

// Sense-reversing global barrier. Safe: all 116 blocks co-resident (116 < 148 SMs).
// Self-cleaning: count returns to 0 each barrier; sense read fresh at kernel entry.
__device__ __forceinline__ void gbar(unsigned* ssense) {
    __syncthreads();
    if (threadIdx.x == 0) {
        unsigned ns = *ssense ^ 1u;
        *ssense = ns;
        __threadfence();
        if (atomicAdd(&g_count, 1u) == GRID - 1) {
            g_count = 0;
            __threadfence();
            g_sense = ns;
        } else {
            while (g_sense != ns) __nanosleep(64);
            __threadfence();
        }
    }
    __syncthreads();
}

__global__ void __launch_bounds__(128, 1) fused(
    const float* __restrict__ enc, const float* __restrict__ ea,
    const float* __restrict__ W_enc, const float* __restrict__ b_enc,
    const float* __restrict__ W1, const float* __restrict__ b1,
    const float* __restrict__ p1, const float* __restrict__ We,
    const float* __restrict__ be, const float* __restrict__ pe,
    const float* __restrict__ W2, const float* __restrict__ b2,
    const float* __restrict__ p2, const float* __restrict__ Wl,
    const float* __restrict__ bl, float* __restrict__ out)
{
    __shared__ __align__(16) float SM[NN * HID];   // z1 cache (ph1); ph0 temps alias
    __shared__ float sWc[256];     // W2 @ Wl, per-block copy
    __shared__ float sd1[116];
    __shared__ float sdv[116];
    __shared__ float sgE[115 * 5];
    __shared__ float sinv[116];
    __shared__ float sS[NN * 5];
    __shared__ float sx1[64];
    __shared__ float sred[640];
    __shared__ float sq4[4];
    __shared__ unsigned s_sense;

    const int i = blockIdx.x, t = threadIdx.x;
    const int p = t >> 6, h = t & 63;
    if (t == 0) s_sense = g_sense;

    // ================= Phase 0: front work =================
    {
        float* encs = SM;            // [122]
        float* x0s  = SM + 128;      // [64]
        float* part = SM + 192;      // [128]
        if (t < ENCD) encs[t] = enc[i * ENCD + t];
        __syncthreads();
        float acc = (p == 0) ? b_enc[h] : 0.f;
        const int k0 = p * 61;
        #pragma unroll 8
        for (int k = k0; k < k0 + 61; ++k) acc += encs[k] * W_enc[k * HID + h];
        part[p * 64 + h] = acc;
        __syncthreads();
        if (t < HID) x0s[t] = part[t] + part[64 + t];
        __syncthreads();
        float az = 0.f;
        const int m0 = p * 32;
        #pragma unroll
        for (int k = m0; k < m0 + 32; ++k) az += x0s[k] * W1[k * HID + h];
        part[p * 64 + h] = az;
        __syncthreads();
        if (t < HID) g_z1[i * HID + t] = part[t] + part[64 + t];

        // edge features: 58 edges per block
        int e = i * 58 + t;
        if (t < 58 && e < NE) {
            float a[5], r[5];
            #pragma unroll
            for (int c = 0; c < 5; c++) { a[c] = ea[e * 5 + c]; r[c] = fmaxf(a[c], 0.f); }
            float d = 0.f;
            #pragma unroll
            for (int c = 0; c < 5; c++) d += a[c] * __ldg(&p1[c]);
            g_d1[e] = d;
            #pragma unroll
            for (int c2 = 0; c2 < 5; c2++) {
                float s = 0.f;
                #pragma unroll
                for (int c = 0; c < 5; c++) s += r[c] * __ldg(&We[c * 5 + c2]);
                g_gE[e * 5 + c2] = s;
            }
        }

        // Wc = W2 @ Wl into smem (redundant per block, no global round-trip)
        for (int idx = t; idx < 256; idx += 128) {
            int k = idx >> 2, o = idx & 3;
            float s = 0.f;
            #pragma unroll 8
            for (int hh = 0; hh < HID; hh++) s += W2[k * HID + hh] * Wl[hh * 4 + o];
            sWc[idx] = s;
        }

        // block 0 seeds output with the bias term: b2@Wl + bl
        if (i == 0 && t < 4) {
            float s = bl[t];
            #pragma unroll 8
            for (int hh = 0; hh < HID; hh++) s += b2[hh] * Wl[hh * 4 + t];
            out[t] = s;
        }
    }
    gbar(&s_sense);

    // ================= Phase 1: node_conv1 -> x1, dv, q =================
    {
        const float4* zg = (const float4*)g_z1;
        float4* zs = (float4*)SM;
        for (int u = t; u < NN * HID / 4; u += 128) zs[u] = zg[u];
        if (t < 115) {
            int k = t + (t >= i);
            int a = min(i, k), b = max(i, k);
            sd1[t] = g_d1[eix(a, b)];
        }
        __syncthreads();

        float acc = p ? 0.f : __ldg(&b1[h]);
        const int u0 = p ? 58 : 0, u1 = p ? 115 : 58;
        #pragma unroll 8
        for (int u = u0; u < u1; ++u) {
            int k = u + (u >= i);
            acc += sd1[u] * SM[k * HID + h];
        }
        sred[p * 64 + h] = acc;
        __syncthreads();
        if (t < HID) sx1[t] = fmaxf(sred[t] + sred[64 + t], 0.f);
        __syncthreads();

        if (t < HID) {
            float xv = sx1[t];
            #pragma unroll
            for (int o = 0; o < 4; o++) sred[t * 5 + o] = xv * sWc[t * 4 + o];
            sred[t * 5 + 4] = xv * __ldg(&pe[t]);
        }
        __syncthreads();
        for (int s = 32; s; s >>= 1) {
            if (t < s) {
                #pragma unroll
                for (int c = 0; c < 5; c++) sred[t * 5 + c] += sred[(t + s) * 5 + c];
            }
            __syncthreads();
        }
        if (t < 4) sq4[t] = sred[t];
        if (t == 4) g_dv[i] = sred[4];
    }
    gbar(&s_sense);

    // ================= Phase 2a: S[i] =================
    {
        if (t < NN) sdv[t] = g_dv[t];
        __syncthreads();
        float a5[5] = {0.f, 0.f, 0.f, 0.f, 0.f};
        if (t < 115) {
            int k = t + (t >= i);
            int a = min(i, k), b = max(i, k);
            int e = eix(a, b);
            float inv = 1.f / (fmaxf(fmaxf(sdv[i], sdv[k]), 0.f) + 1e-10f);
            sinv[t] = inv;
            #pragma unroll
            for (int c = 0; c < 5; c++) {
                float g = g_gE[e * 5 + c];
                sgE[t * 5 + c] = g;
                a5[c] = g * inv;
            }
        }
        #pragma unroll
        for (int c = 0; c < 5; c++) sred[t * 5 + c] = a5[c];
        __syncthreads();
        for (int s = 64; s; s >>= 1) {
            if (t < s) {
                #pragma unroll
                for (int c = 0; c < 5; c++) sred[t * 5 + c] += sred[(t + s) * 5 + c];
            }
            __syncthreads();
        }
        if (t < 5) g_S[i * 5 + t] = sred[t];
    }
    gbar(&s_sense);

    // ================= Phase 2b: D[i] and output RED =================
    {
        for (int u = t; u < NN * 5; u += 128) sS[u] = g_S[u];
        __syncthreads();
        float partv = 0.f;
        float dvj = sdv[i];
        if (t < 115) {
            int k = t + (t >= i);
            float dvk = sdv[k];
            float iv = sinv[t];
            #pragma unroll
            for (int c = 0; c < 5; c++) {
                float hh = sgE[t * 5 + c] * iv;
                float v = dvj * (sS[i * 5 + c] - hh) + dvk * (sS[k * 5 + c] - hh) + __ldg(&be[c]);
                partv += fmaxf(v, 0.f) * __ldg(&p2[c]);
            }
        }
        sred[t] = partv;
        __syncthreads();
        for (int s = 64; s; s >>= 1) {
            if (t < s) sred[t] += sred[t + s];
            __syncthreads();
        }
        if (t < 4) atomicAdd(&out[t], sred[0] * (1.0f / (float)NN) * sq4[t]);
    }
}

extern "C" void kernel_launch(void* const* d_in, const int* in_sizes, int n_in,
                              void* d_out, int out_size) {
    const float* enc   = (const float*)d_in[0];
    const float* ea    = (const float*)d_in[1];
    // d_in[2] = edge_index (triu order, closed-form reproduced) — unused
    const float* W_enc = (const float*)d_in[3];
    const float* b_enc = (const float*)d_in[4];
    const float* W1    = (const float*)d_in[5];
    const float* b1    = (const float*)d_in[6];
    const float* p1    = (const float*)d_in[7];
    const float* We    = (const float*)d_in[8];
    const float* be    = (const float*)d_in[9];
    const float* pe    = (const float*)d_in[10];
    const float* W2    = (const float*)d_in[11];
    const float* b2    = (const float*)d_in[12];
    const float* p2    = (const float*)d_in[13];
    const float* Wl    = (const float*)d_in[14];
    const float* bl    = (const float*)d_in[15];
    float* out = (float*)d_out;

    fused<<<GRID, 128>>>(enc, ea, W_enc, b_enc, W1, b1, p1, We, be, pe,
                         W2, b2, p2, Wl, bl, out);
}

// round 3
// speedup vs baseline: 1.0616x; 1.0616x over previous
#include <cuda_runtime.h>

#define NN   116
#define NE   6670
#define HID  64
#define ENCD 122
#define GRID 16
#define NT   256

// ---- device scratch ----
__device__ __align__(16) float g_z1[NN * HID];
__device__ float g_d1[NE];
__device__ float g_gE[NE * 5];
__device__ float g_dv[NN];
__device__ float g_S[NN * 5];
__device__ unsigned g_count = 0;
__device__ unsigned g_gen = 0;

__device__ __forceinline__ int eix(int a, int b) {  // a < b, triu order
    return a * (231 - a) / 2 + (b - a - 1);
}

// Generation-counter grid barrier: 16 co-resident blocks, no sense reset needed,
// monotone gen survives graph replays. No nanosleep (wakeup quantization hurt R2).
__device__ __forceinline__ void gbar() {
    __syncthreads();
    if (threadIdx.x == 0) {
        unsigned gen = *(volatile unsigned*)&g_gen;
        __threadfence();
        if (atomicAdd(&g_count, 1u) == GRID - 1) {
            g_count = 0;
            __threadfence();
            atomicAdd(&g_gen, 1u);
        } else {
            while (*(volatile unsigned*)&g_gen == gen) {}
        }
        __threadfence();
    }
    __syncthreads();
}

__global__ void __launch_bounds__(NT, 1) fused(
    const float* __restrict__ enc, const float* __restrict__ ea,
    const float* __restrict__ W_enc, const float* __restrict__ b_enc,
    const float* __restrict__ W1, const float* __restrict__ b1,
    const float* __restrict__ p1, const float* __restrict__ We,
    const float* __restrict__ be, const float* __restrict__ pe,
    const float* __restrict__ W2, const float* __restrict__ b2,
    const float* __restrict__ p2, const float* __restrict__ Wl,
    const float* __restrict__ bl, float* __restrict__ out)
{
    __shared__ __align__(16) float z1s[NN * HID];  // ph1; ph0 temps alias front
    __shared__ float sWc[HID * 4];
    __shared__ float sd1[8 * 115];
    __shared__ float sq[8 * 4];
    __shared__ float sdv[NN];
    __shared__ float sS[NN * 5];
    __shared__ float wsum[8 * 5];
    __shared__ float sacc[4];

    const int b = blockIdx.x, t = threadIdx.x;
    const int base = (b < 4) ? 8 * b : 32 + 7 * (b - 4);
    const int cnt  = (b < 4) ? 8 : 7;
    const int sub = t >> 6, h = t & 63;
    const int wq = t >> 5, lane = t & 31;

    // ================= Phase 0 =================
    {
        float* encs = z1s;          // [4*122]
        float* x0s  = z1s + 512;    // [4*64]
        for (int g = 0; g < 2; ++g) {
            __syncthreads();
            for (int idx = t; idx < 4 * ENCD; idx += NT) {
                int s = idx / ENCD, k = idx - s * ENCD;
                int i = min(base + g * 4 + s, NN - 1);
                encs[idx] = enc[i * ENCD + k];
            }
            __syncthreads();
            float acc = b_enc[h];
            #pragma unroll 8
            for (int k = 0; k < ENCD; ++k) acc += encs[sub * ENCD + k] * W_enc[k * HID + h];
            x0s[sub * HID + h] = acc;
            __syncthreads();
            float az = 0.f;
            #pragma unroll 8
            for (int k = 0; k < HID; ++k) az += x0s[sub * HID + k] * W1[k * HID + h];
            int nl = g * 4 + sub;
            if (nl < cnt) g_z1[(base + nl) * HID + h] = az;
        }
        // edge features (strided across grid)
        for (int e = b * NT + t; e < NE; e += GRID * NT) {
            float a[5], r[5];
            #pragma unroll
            for (int c = 0; c < 5; c++) { a[c] = ea[e * 5 + c]; r[c] = fmaxf(a[c], 0.f); }
            float d = 0.f;
            #pragma unroll
            for (int c = 0; c < 5; c++) d += a[c] * p1[c];
            g_d1[e] = d;
            #pragma unroll
            for (int c2 = 0; c2 < 5; c2++) {
                float s = 0.f;
                #pragma unroll
                for (int c = 0; c < 5; c++) s += r[c] * We[c * 5 + c2];
                g_gE[e * 5 + c2] = s;
            }
        }
        // Wc = W2 @ Wl  (t exactly covers 64*4)
        {
            int k = t >> 2, o = t & 3;
            float s = 0.f;
            #pragma unroll 8
            for (int hh = 0; hh < HID; hh++) s += W2[k * HID + hh] * Wl[hh * 4 + o];
            sWc[t] = s;
        }
        if (b == 0 && t < 4) {
            float s = bl[t];
            #pragma unroll 8
            for (int hh = 0; hh < HID; hh++) s += b2[hh] * Wl[hh * 4 + t];
            out[t] = s;
        }
    }
    gbar();

    // ================= Phase 1: node_conv1 -> x1, dv, q =================
    {
        const float4* zg = (const float4*)g_z1;
        float4* zs = (float4*)z1s;
        for (int u = t; u < NN * HID / 4; u += NT) zs[u] = zg[u];
        for (int idx = t; idx < 8 * 115; idx += NT) {
            int nl = idx / 115, u = idx - nl * 115;
            int i = min(base + nl, NN - 1);
            int k = u + (u >= i);
            sd1[idx] = g_d1[eix(min(i, k), max(i, k))];
        }
        __syncthreads();
        for (int g = 0; g < 2; ++g) {
            int nl = g * 4 + sub;
            int i = min(base + nl, NN - 1);
            float acc = b1[h];
            const float* drow = sd1 + nl * 115;
            #pragma unroll 4
            for (int u = 0; u < i; ++u)   acc += drow[u] * z1s[u * HID + h];
            #pragma unroll 4
            for (int u = i; u < 115; ++u) acc += drow[u] * z1s[(u + 1) * HID + h];
            float x1 = fmaxf(acc, 0.f);
            float p5[5];
            #pragma unroll
            for (int o = 0; o < 4; o++) p5[o] = x1 * sWc[h * 4 + o];
            p5[4] = x1 * pe[h];
            #pragma unroll
            for (int c = 0; c < 5; c++) {
                float v = p5[c];
                #pragma unroll
                for (int off = 16; off; off >>= 1) v += __shfl_down_sync(0xffffffffu, v, off);
                if (lane == 0) wsum[wq * 5 + c] = v;
            }
            __syncthreads();
            if (t < 20) {
                int s = t / 5, c = t - 5 * s;
                float v = wsum[(2 * s) * 5 + c] + wsum[(2 * s + 1) * 5 + c];
                int n2 = g * 4 + s;
                if (n2 < cnt) {
                    if (c < 4) sq[n2 * 4 + c] = v;
                    else       g_dv[base + n2] = v;
                }
            }
            __syncthreads();
        }
    }
    gbar();

    // ================= Phase 2a: S[i] (warp per node) =================
    {
        if (t < NN) sdv[t] = g_dv[t];
        __syncthreads();
        int i = min(base + wq, NN - 1);
        bool valid = wq < cnt;
        float dvi = sdv[i];
        float a5[5] = {0.f, 0.f, 0.f, 0.f, 0.f};
        #pragma unroll
        for (int q = 0; q < 4; ++q) {
            int u = lane + q * 32;
            if (u < 115) {
                int k = u + (u >= i);
                int e = eix(min(i, k), max(i, k));
                float inv = 1.f / (fmaxf(fmaxf(dvi, sdv[k]), 0.f) + 1e-10f);
                #pragma unroll
                for (int c = 0; c < 5; c++) a5[c] += g_gE[e * 5 + c] * inv;
            }
        }
        #pragma unroll
        for (int c = 0; c < 5; c++) {
            #pragma unroll
            for (int off = 16; off; off >>= 1) a5[c] += __shfl_down_sync(0xffffffffu, a5[c], off);
        }
        if (lane == 0 && valid) {
            #pragma unroll
            for (int c = 0; c < 5; c++) g_S[i * 5 + c] = a5[c];
        }
    }
    gbar();

    // ================= Phase 2b: D[i], accumulate output =================
    {
        for (int u = t; u < NN * 5; u += NT) sS[u] = g_S[u];
        if (t < 4) sacc[t] = 0.f;
        __syncthreads();
        int i = min(base + wq, NN - 1);
        bool valid = wq < cnt;
        float dvi = sdv[i];
        float partv = 0.f;
        #pragma unroll
        for (int q = 0; q < 4; ++q) {
            int u = lane + q * 32;
            if (u < 115) {
                int k = u + (u >= i);
                int e = eix(min(i, k), max(i, k));
                float dvk = sdv[k];
                float inv = 1.f / (fmaxf(fmaxf(dvi, dvk), 0.f) + 1e-10f);
                #pragma unroll
                for (int c = 0; c < 5; c++) {
                    float hh = g_gE[e * 5 + c] * inv;
                    float v = dvi * (sS[i * 5 + c] - hh) + dvk * (sS[k * 5 + c] - hh) + be[c];
                    partv += fmaxf(v, 0.f) * p2[c];
                }
            }
        }
        #pragma unroll
        for (int off = 16; off; off >>= 1) partv += __shfl_down_sync(0xffffffffu, partv, off);
        partv = __shfl_sync(0xffffffffu, partv, 0);
        if (valid && lane < 4)
            atomicAdd(&sacc[lane], partv * (1.0f / (float)NN) * sq[wq * 4 + lane]);
        __syncthreads();
        if (t < 4) atomicAdd(&out[t], sacc[t]);
    }
}

extern "C" void kernel_launch(void* const* d_in, const int* in_sizes, int n_in,
                              void* d_out, int out_size) {
    const float* enc   = (const float*)d_in[0];
    const float* ea    = (const float*)d_in[1];
    // d_in[2] = edge_index (triu order, closed-form reproduced) — unused
    const float* W_enc = (const float*)d_in[3];
    const float* b_enc = (const float*)d_in[4];
    const float* W1    = (const float*)d_in[5];
    const float* b1    = (const float*)d_in[6];
    const float* p1    = (const float*)d_in[7];
    const float* We    = (const float*)d_in[8];
    const float* be    = (const float*)d_in[9];
    const float* pe    = (const float*)d_in[10];
    const float* W2    = (const float*)d_in[11];
    const float* b2    = (const float*)d_in[12];
    const float* p2    = (const float*)d_in[13];
    const float* Wl    = (const float*)d_in[14];
    const float* bl    = (const float*)d_in[15];
    float* out = (float*)d_out;

    fused<<<GRID, NT>>>(enc, ea, W_enc, b_enc, W1, b1, p1, We, be, pe,
                        W2, b2, p2, Wl, bl, out);
}